// round 14
// baseline (speedup 1.0000x reference)
#include <cuda_runtime.h>

#define TT 2048
#define NB 512
#define FULLM 0xFFFFFFFFu
typedef unsigned long long ull;

__device__ __forceinline__ float tanhap(float x) {
    float r; asm("tanh.approx.f32 %0, %1;" : "=f"(r) : "f"(x)); return r;
}
__device__ __forceinline__ ull pk(float lo, float hi) {
    ull r; asm("mov.b64 %0, {%1, %2};" : "=l"(r) : "f"(lo), "f"(hi)); return r;
}
__device__ __forceinline__ void upk(ull v, float& lo, float& hi) {
    asm("mov.b64 {%0, %1}, %2;" : "=f"(lo), "=f"(hi) : "l"(v));
}
__device__ __forceinline__ ull fma2(ull a, ull b, ull c) {
    ull d; asm("fma.rn.f32x2 %0, %1, %2, %3;" : "=l"(d) : "l"(a), "l"(b), "l"(c)); return d;
}
__device__ __forceinline__ ull add2(ull a, ull b) {
    ull d; asm("add.rn.f32x2 %0, %1, %2;" : "=l"(d) : "l"(a), "l"(b)); return d;
}
__device__ __forceinline__ ull d2l(double d) { return (ull)__double_as_longlong(d); }

__device__ __forceinline__ void cp_async4(void* smem_dst, const void* gmem_src) {
    unsigned saddr = (unsigned)__cvta_generic_to_shared(smem_dst);
    asm volatile("cp.async.ca.shared.global [%0], [%1], 4;\n"
                 :: "r"(saddr), "l"(gmem_src) : "memory");
}
__device__ __forceinline__ void cp_commit() {
    asm volatile("cp.async.commit_group;\n" ::: "memory");
}
__device__ __forceinline__ void cp_wait1() {
    asm volatile("cp.async.wait_group 1;\n" ::: "memory");
}

__global__ void __launch_bounds__(32)
lstm_typed(const float* __restrict__ x,
           const float* __restrict__ W_ih,
           const float* __restrict__ W_hh,
           const float* __restrict__ b_ih,
           const float* __restrict__ b_hh,
           const float* __restrict__ fc_w,
           const float* __restrict__ fc_b,
           float* __restrict__ out)
{
    // 16-deep x ring (32-wide rows; all lanes fetch, clamped) and typed
    // double-buffered h rows (32-wide so the STS is unconditional).
    __shared__ __align__(16) float xring[16][32];
    __shared__ __align__(16) float hbuf[2][32];

    const int lane = threadIdx.x & 31;
    const int seq  = blockIdx.x;
    const float* xb = x + (size_t)seq * TT * 13;
    float* ob = out + (size_t)seq * TT;

    const int kcl = (lane < 13) ? lane : 12;   // clamped x element

    hbuf[0][lane] = 0.0f;
    hbuf[1][lane] = 0.0f;

    // Lane L<26: A = gate L (sigmoid: i for L<13, f else), B = gate 26+L
    // (g=tanh for L<13, o=sigmoid else). Lane 26: B-dot = FC head.
    // Sigmoid pre-scale 0.5 folded into weights: act = m*tanh(pre)+a.
    float wiA[13], whAs[13], wiB[13], whBs[13];
    float biasA = 0.0f, biasB = 0.0f;
    {
        const bool g26 = (lane < 26);
        const float sA = 0.5f;
        const float sB = (lane < 13) ? 1.0f : 0.5f;
        const int rA = g26 ? lane : 0;
        const int rB = g26 ? lane + 26 : 0;
        #pragma unroll
        for (int k = 0; k < 13; k++) {
            wiA[k]  = g26 ? sA * W_ih[rA * 13 + k] : 0.0f;
            whAs[k] = g26 ? sA * W_hh[rA * 13 + k] : 0.0f;
            wiB[k]  = g26 ? sB * W_ih[rB * 13 + k] : 0.0f;
            whBs[k] = g26 ? sB * W_hh[rB * 13 + k] : 0.0f;
        }
        if (g26) {
            biasA = sA * (b_ih[rA] + b_hh[rA]);
            biasB = sB * (b_ih[rB] + b_hh[rB]);
        }
        if (lane == 26) {
            #pragma unroll
            for (int k = 0; k < 13; k++) { wiB[k] = 0.0f; whBs[k] = 0.5f * fc_w[k]; }
            biasB = 0.5f * fc_b[0];
        }
    }

    ull wxA[7], whA[7], wxB[7], whB[7];
    #pragma unroll
    for (int p = 0; p < 6; p++) {
        wxA[p] = pk(wiA[2*p],  wiA[2*p+1]);
        whA[p] = pk(whAs[2*p], whAs[2*p+1]);
        wxB[p] = pk(wiB[2*p],  wiB[2*p+1]);
        whB[p] = pk(whBs[2*p], whBs[2*p+1]);
    }
    wxA[6] = pk(wiA[12],  0.0f);
    whA[6] = pk(whAs[12], 0.0f);
    wxB[6] = pk(wiB[12],  0.0f);
    whB[6] = pk(whBs[12], 0.0f);

    const ull biasPA = pk(biasA, 0.0f);
    const ull biasPB = pk(biasB, 0.0f);
    const ull z64    = pk(0.0f, 0.0f);

    const float mB = (lane < 13) ? 1.0f : 0.5f;
    const float aB = (lane < 13) ? 0.0f : 0.5f;

    float h = 0.0f, c = 0.0f;

    // Prologue: stage rows 0..7 as ONE commit group.
    #pragma unroll
    for (int r = 0; r < 8; r++)
        cp_async4(&xring[r][lane], xb + r * 13 + kcl);
    cp_commit();

// One step. SLOT: compile-time x slot (synced at block entry). RB/WB: h
// parity. h goes through TYPED float smem: no volatile, no syncwarp — the
// compiler preserves ST->LD order via may-alias analysis, the in-order LSU
// preserves it in hardware, and ptxas keeps full scheduling freedom.
#define STEP(SLOT, RB, WB, TTC) do {                                           \
    float hk[13];                                                              \
    _Pragma("unroll")                                                          \
    for (int k = 0; k < 13; k++) hk[k] = hbuf[(RB)][k];                        \
    const ull hp0 = pk(hk[0],  hk[1]);                                         \
    const ull hp1 = pk(hk[2],  hk[3]);                                         \
    const ull hp2 = pk(hk[4],  hk[5]);                                         \
    const ull hp3 = pk(hk[6],  hk[7]);                                         \
    const ull hp4 = pk(hk[8],  hk[9]);                                         \
    const ull hp5 = pk(hk[10], hk[11]);                                        \
    const ull hp6 = pk(hk[12], 0.0f);                                          \
    const double2* xr = reinterpret_cast<const double2*>(&xring[(SLOT)][0]);   \
    const double2 q0 = xr[0], q1 = xr[1], q2 = xr[2];                          \
    const double  q3 = *reinterpret_cast<const double*>(&xring[(SLOT)][12]);   \
    const ull xp0 = d2l(q0.x), xp1 = d2l(q0.y), xp2 = d2l(q1.x),               \
              xp3 = d2l(q1.y), xp4 = d2l(q2.x), xp5 = d2l(q2.y),               \
              xp6 = d2l(q3);                                                   \
    /* gate A: 4 chains, x first, h enters at depth <=2 */                     \
    ull a0 = fma2(xp0, wxA[0], biasPA);                                        \
    ull a1 = fma2(xp1, wxA[1], z64);                                           \
    ull a2 = fma2(xp2, wxA[2], z64);                                           \
    ull a3 = fma2(xp3, wxA[3], z64);                                           \
    a0 = fma2(xp4, wxA[4], a0);                                                \
    a1 = fma2(xp5, wxA[5], a1);                                                \
    a2 = fma2(xp6, wxA[6], a2);                                                \
    a3 = fma2(hp0, whA[0], a3);                                                \
    a0 = fma2(hp1, whA[1], a0);                                                \
    a1 = fma2(hp2, whA[2], a1);                                                \
    a2 = fma2(hp3, whA[3], a2);                                                \
    a3 = fma2(hp4, whA[4], a3);                                                \
    a0 = fma2(hp5, whA[5], a0);                                                \
    a1 = fma2(hp6, whA[6], a1);                                                \
    const ull sA = add2(add2(a0, a1), add2(a2, a3));                           \
    /* gate B */                                                               \
    ull b0 = fma2(xp0, wxB[0], biasPB);                                        \
    ull b1 = fma2(xp1, wxB[1], z64);                                           \
    ull b2 = fma2(xp2, wxB[2], z64);                                           \
    ull b3 = fma2(xp3, wxB[3], z64);                                           \
    b0 = fma2(xp4, wxB[4], b0);                                                \
    b1 = fma2(xp5, wxB[5], b1);                                                \
    b2 = fma2(xp6, wxB[6], b2);                                                \
    b3 = fma2(hp0, whB[0], b3);                                                \
    b0 = fma2(hp1, whB[1], b0);                                                \
    b1 = fma2(hp2, whB[2], b1);                                                \
    b2 = fma2(hp3, whB[3], b2);                                                \
    b3 = fma2(hp4, whB[4], b3);                                                \
    b0 = fma2(hp5, whB[5], b0);                                                \
    b1 = fma2(hp6, whB[6], b1);                                                \
    const ull sB = add2(add2(b0, b1), add2(b2, b3));                           \
    float sa0, sa1, sb0, sb1;                                                  \
    upk(sA, sa0, sa1); upk(sB, sb0, sb1);                                      \
    const float preA = sa0 + sa1;                                              \
    const float preB = sb0 + sb1;                                              \
    const float actA = fmaf(0.5f, tanhap(preA), 0.5f);                         \
    const float actB = fmaf(mB,   tanhap(preB), aB);                           \
    int ttm = (TTC) - 1;                                                       \
    ttm = (ttm < 0) ? 0 : ttm;       /* ob[0] garbage, overwritten at t=1 */   \
    if (lane == 26) ob[ttm] = actB;                                            \
    const float fg = __shfl_sync(FULLM, actA, (lane + 13) & 31);               \
    const float og = __shfl_sync(FULLM, actB, (lane + 13) & 31);               \
    c = fmaf(fg, c, actA * actB);                                              \
    h = og * tanhap(c);                                                        \
    hbuf[(WB)][lane] = h;            /* unconditional; pads never read */      \
} while (0)

    for (int t = 0; t < TT; t += 16) {
        // Half 0: issue rows t+8..t+15 (slots 8..15); process slots 0..7.
        #pragma unroll
        for (int r = 0; r < 8; r++) {
            int row = t + 8 + r;
            row = (row > TT - 1) ? (TT - 1) : row;
            cp_async4(&xring[8 + r][lane], xb + (size_t)row * 13 + kcl);
        }
        cp_commit();
        cp_wait1();          // rows t..t+7 resident
        __syncwarp();        // one visibility + ordering barrier per 8 steps
        STEP(0, 1, 0, t + 0);
        STEP(1, 0, 1, t + 1);
        STEP(2, 1, 0, t + 2);
        STEP(3, 0, 1, t + 3);
        STEP(4, 1, 0, t + 4);
        STEP(5, 0, 1, t + 5);
        STEP(6, 1, 0, t + 6);
        STEP(7, 0, 1, t + 7);

        // Half 1: issue rows t+16..t+23 (slots 0..7); process slots 8..15.
        #pragma unroll
        for (int r = 0; r < 8; r++) {
            int row = t + 16 + r;
            row = (row > TT - 1) ? (TT - 1) : row;
            cp_async4(&xring[r][lane], xb + (size_t)row * 13 + kcl);
        }
        cp_commit();
        cp_wait1();          // rows t+8..t+15 resident
        __syncwarp();
        STEP( 8, 1, 0, t +  8);
        STEP( 9, 0, 1, t +  9);
        STEP(10, 1, 0, t + 10);
        STEP(11, 0, 1, t + 11);
        STEP(12, 1, 0, t + 12);
        STEP(13, 0, 1, t + 13);
        STEP(14, 1, 0, t + 14);
        STEP(15, 0, 1, t + 15);
    }
#undef STEP

    // Tail: ob[TT-1] = sigm(fc(h_{TT-1})); step 2047 wrote hbuf[1].
    __syncwarp();
    {
        float hk[13];
        #pragma unroll
        for (int k = 0; k < 13; k++) hk[k] = hbuf[1][k];
        float s0 = biasB, s1 = 0.0f, s2 = 0.0f, s3 = 0.0f;
        #pragma unroll
        for (int k = 0; k < 13; k++) {
            switch (k & 3) {
                case 0: s0 = fmaf(hk[k], whBs[k], s0); break;
                case 1: s1 = fmaf(hk[k], whBs[k], s1); break;
                case 2: s2 = fmaf(hk[k], whBs[k], s2); break;
                case 3: s3 = fmaf(hk[k], whBs[k], s3); break;
            }
        }
        const float pre  = (s0 + s1) + (s2 + s3);
        const float outv = fmaf(0.5f, tanhap(pre), 0.5f);
        if (lane == 26) ob[TT - 1] = outv;
    }
}

extern "C" void kernel_launch(void* const* d_in, const int* in_sizes, int n_in,
                              void* d_out, int out_size) {
    (void)in_sizes; (void)n_in; (void)out_size;
    const float* x    = (const float*)d_in[0];
    const float* W_ih = (const float*)d_in[1];
    const float* W_hh = (const float*)d_in[2];
    const float* b_ih = (const float*)d_in[3];
    const float* b_hh = (const float*)d_in[4];
    const float* fc_w = (const float*)d_in[5];
    const float* fc_b = (const float*)d_in[6];
    float* out = (float*)d_out;

    lstm_typed<<<NB, 32>>>(x, W_ih, W_hh, b_ih, b_hh, fc_w, fc_b, out);
}

// round 15
// speedup vs baseline: 1.1664x; 1.1664x over previous
#include <cuda_runtime.h>

#define TT 2048
#define NB 512
#define FULLM 0xFFFFFFFFu
typedef unsigned long long ull;

__device__ __forceinline__ float tanhap(float x) {
    float r; asm("tanh.approx.f32 %0, %1;" : "=f"(r) : "f"(x)); return r;
}
__device__ __forceinline__ ull pk(float lo, float hi) {
    ull r; asm("mov.b64 %0, {%1, %2};" : "=l"(r) : "f"(lo), "f"(hi)); return r;
}
__device__ __forceinline__ void upk(ull v, float& lo, float& hi) {
    asm("mov.b64 {%0, %1}, %2;" : "=f"(lo), "=f"(hi) : "l"(v));
}
__device__ __forceinline__ ull fma2(ull a, ull b, ull c) {
    ull d; asm("fma.rn.f32x2 %0, %1, %2, %3;" : "=l"(d) : "l"(a), "l"(b), "l"(c)); return d;
}
__device__ __forceinline__ ull add2(ull a, ull b) {
    ull d; asm("add.rn.f32x2 %0, %1, %2;" : "=l"(d) : "l"(a), "l"(b)); return d;
}
__device__ __forceinline__ ull d2l(double d) { return (ull)__double_as_longlong(d); }

__device__ __forceinline__ void cp_async4(void* smem_dst, const void* gmem_src) {
    unsigned saddr = (unsigned)__cvta_generic_to_shared(smem_dst);
    asm volatile("cp.async.ca.shared.global [%0], [%1], 4;\n"
                 :: "r"(saddr), "l"(gmem_src) : "memory");
}
__device__ __forceinline__ void cp_commit() {
    asm volatile("cp.async.commit_group;\n" ::: "memory");
}
__device__ __forceinline__ void cp_wait1() {
    asm volatile("cp.async.wait_group 1;\n" ::: "memory");
}

__device__ __forceinline__ void ldpairs(const float* row, ull* p) {
    const double2* r = reinterpret_cast<const double2*>(row);
    const double2 q0 = r[0], q1 = r[1], q2 = r[2];
    const double  q3 = *reinterpret_cast<const double*>(row + 12);
    p[0] = d2l(q0.x); p[1] = d2l(q0.y); p[2] = d2l(q1.x); p[3] = d2l(q1.y);
    p[4] = d2l(q2.x); p[5] = d2l(q2.y); p[6] = d2l(q3);
}

__global__ void __launch_bounds__(32)
lstm_r15(const float* __restrict__ x,
         const float* __restrict__ W_ih,
         const float* __restrict__ W_hh,
         const float* __restrict__ b_ih,
         const float* __restrict__ b_hh,
         const float* __restrict__ fc_w,
         const float* __restrict__ fc_b,
         float* __restrict__ out)
{
    // 16-deep x ring (rows padded to 16 floats; pads zero) + double-buffered h.
    __shared__ __align__(16) float xring[16][16];
    __shared__ __align__(16) float hbuf[2][16];

    const int lane = threadIdx.x & 31;
    const int seq  = blockIdx.x;
    const float* xb = x + (size_t)seq * TT * 13;
    float* ob = out + (size_t)seq * TT;

    // Zero ring pads + h buffers once (cp.async only writes [0..12]).
    #pragma unroll
    for (int i = 0; i < 8; i++)
        reinterpret_cast<float*>(xring)[i * 32 + lane] = 0.0f;
    if (lane < 16) { hbuf[0][lane] = 0.0f; hbuf[1][lane] = 0.0f; }

    // Lane L<26: A = gate L (sigmoid: i for L<13, f else), B = gate 26+L
    // (g=tanh for L<13, o=sigmoid else). Lane 26: B-dot = FC head.
    // Sigmoid pre-scale 0.5 folded into weights: act = m*tanh(pre)+a.
    float wiA[13], whAs[13], wiB[13], whBs[13];
    float biasA = 0.0f, biasB = 0.0f;
    {
        const bool g26 = (lane < 26);
        const float sA = 0.5f;
        const float sB = (lane < 13) ? 1.0f : 0.5f;
        const int rA = g26 ? lane : 0;
        const int rB = g26 ? lane + 26 : 0;
        #pragma unroll
        for (int k = 0; k < 13; k++) {
            wiA[k]  = g26 ? sA * W_ih[rA * 13 + k] : 0.0f;
            whAs[k] = g26 ? sA * W_hh[rA * 13 + k] : 0.0f;
            wiB[k]  = g26 ? sB * W_ih[rB * 13 + k] : 0.0f;
            whBs[k] = g26 ? sB * W_hh[rB * 13 + k] : 0.0f;
        }
        if (g26) {
            biasA = sA * (b_ih[rA] + b_hh[rA]);
            biasB = sB * (b_ih[rB] + b_hh[rB]);
        }
        if (lane == 26) {
            #pragma unroll
            for (int k = 0; k < 13; k++) { wiB[k] = 0.0f; whBs[k] = 0.5f * fc_w[k]; }
            biasB = 0.5f * fc_b[0];
        }
    }

    ull wxA[7], whA[7], wxB[7], whB[7];
    #pragma unroll
    for (int p = 0; p < 6; p++) {
        wxA[p] = pk(wiA[2*p],  wiA[2*p+1]);
        whA[p] = pk(whAs[2*p], whAs[2*p+1]);
        wxB[p] = pk(wiB[2*p],  wiB[2*p+1]);
        whB[p] = pk(whBs[2*p], whBs[2*p+1]);
    }
    wxA[6] = pk(wiA[12],  0.0f);
    whA[6] = pk(whAs[12], 0.0f);
    wxB[6] = pk(wiB[12],  0.0f);
    whB[6] = pk(whBs[12], 0.0f);

    const ull biasPA = pk(biasA, 0.0f);
    const ull biasPB = pk(biasB, 0.0f);
    const ull z64    = pk(0.0f, 0.0f);

    const float mB = (lane < 13) ? 1.0f : 0.5f;
    const float aB = (lane < 13) ? 0.0f : 0.5f;

    float h = 0.0f, c = 0.0f;

    // Prologue: stage rows 0..7 as ONE commit group.
    #pragma unroll
    for (int r = 0; r < 8; r++)
        if (lane < 13) cp_async4(&xring[r][lane], xb + r * 13 + lane);
    cp_commit();

// One step: R5's exact h path (one __syncwarp then wide double2 reads),
// compile-time x slot, 4-chain packed dots, activated f/o shipped by shfl.
#define STEP(SLOT, RB, WB, TTC) do {                                           \
    __syncwarp();                    /* orders prev STS h before reads */      \
    ull hp[7];                                                                 \
    ldpairs(&hbuf[(RB)][0], hp);                                               \
    ull xp[7];                                                                 \
    ldpairs(&xring[(SLOT)][0], xp);                                            \
    /* gate A: x first, h enters at depth <= 2 */                              \
    ull a0 = fma2(xp[0], wxA[0], biasPA);                                      \
    ull a1 = fma2(xp[1], wxA[1], z64);                                         \
    ull a2 = fma2(xp[2], wxA[2], z64);                                         \
    ull a3 = fma2(xp[3], wxA[3], z64);                                         \
    a0 = fma2(xp[4], wxA[4], a0);                                              \
    a1 = fma2(xp[5], wxA[5], a1);                                              \
    a2 = fma2(xp[6], wxA[6], a2);                                              \
    a3 = fma2(hp[0], whA[0], a3);                                              \
    a0 = fma2(hp[1], whA[1], a0);                                              \
    a1 = fma2(hp[2], whA[2], a1);                                              \
    a2 = fma2(hp[3], whA[3], a2);                                              \
    a3 = fma2(hp[4], whA[4], a3);                                              \
    a0 = fma2(hp[5], whA[5], a0);                                              \
    a1 = fma2(hp[6], whA[6], a1);                                              \
    const ull sA = add2(add2(a0, a1), add2(a2, a3));                           \
    /* gate B */                                                               \
    ull b0 = fma2(xp[0], wxB[0], biasPB);                                      \
    ull b1 = fma2(xp[1], wxB[1], z64);                                         \
    ull b2 = fma2(xp[2], wxB[2], z64);                                         \
    ull b3 = fma2(xp[3], wxB[3], z64);                                         \
    b0 = fma2(xp[4], wxB[4], b0);                                              \
    b1 = fma2(xp[5], wxB[5], b1);                                              \
    b2 = fma2(xp[6], wxB[6], b2);                                              \
    b3 = fma2(hp[0], whB[0], b3);                                              \
    b0 = fma2(hp[1], whB[1], b0);                                              \
    b1 = fma2(hp[2], whB[2], b1);                                              \
    b2 = fma2(hp[3], whB[3], b2);                                              \
    b3 = fma2(hp[4], whB[4], b3);                                              \
    b0 = fma2(hp[5], whB[5], b0);                                              \
    b1 = fma2(hp[6], whB[6], b1);                                              \
    const ull sB = add2(add2(b0, b1), add2(b2, b3));                           \
    float sa0, sa1, sb0, sb1;                                                  \
    upk(sA, sa0, sa1); upk(sB, sb0, sb1);                                      \
    const float preA = sa0 + sa1;                                              \
    const float preB = sb0 + sb1;                                              \
    const float actA = fmaf(0.5f, tanhap(preA), 0.5f);                         \
    const float actB = fmaf(mB,   tanhap(preB), aB);                           \
    if (lane == 26 && (TTC) > 0) ob[(TTC) - 1] = actB;                         \
    const float fg = __shfl_sync(FULLM, actA, (lane + 13) & 31);               \
    const float og = __shfl_sync(FULLM, actB, (lane + 13) & 31);               \
    c = fmaf(fg, c, actA * actB);                                              \
    h = og * tanhap(c);                                                        \
    if (lane < 13) hbuf[(WB)][lane] = h;                                       \
} while (0)

    for (int t = 0; t < TT; t += 16) {
        // Half 0: issue rows t+8..t+15 (slots 8..15); process slots 0..7.
        #pragma unroll
        for (int r = 0; r < 8; r++) {
            int row = t + 8 + r;
            row = (row > TT - 1) ? (TT - 1) : row;
            if (lane < 13) cp_async4(&xring[8 + r][lane], xb + (size_t)row * 13 + lane);
        }
        cp_commit();
        cp_wait1();          // rows t..t+7 resident
        STEP(0, 1, 0, t + 0);
        STEP(1, 0, 1, t + 1);
        STEP(2, 1, 0, t + 2);
        STEP(3, 0, 1, t + 3);
        STEP(4, 1, 0, t + 4);
        STEP(5, 0, 1, t + 5);
        STEP(6, 1, 0, t + 6);
        STEP(7, 0, 1, t + 7);

        // Half 1: issue rows t+16..t+23 (slots 0..7); process slots 8..15.
        #pragma unroll
        for (int r = 0; r < 8; r++) {
            int row = t + 16 + r;
            row = (row > TT - 1) ? (TT - 1) : row;
            if (lane < 13) cp_async4(&xring[r][lane], xb + (size_t)row * 13 + lane);
        }
        cp_commit();
        cp_wait1();          // rows t+8..t+15 resident
        STEP( 8, 1, 0, t +  8);
        STEP( 9, 0, 1, t +  9);
        STEP(10, 1, 0, t + 10);
        STEP(11, 0, 1, t + 11);
        STEP(12, 1, 0, t + 12);
        STEP(13, 0, 1, t + 13);
        STEP(14, 1, 0, t + 14);
        STEP(15, 0, 1, t + 15);
    }
#undef STEP

    // Tail: ob[TT-1] = sigm(fc(h_{TT-1})); step 2047 wrote hbuf[1].
    __syncwarp();
    {
        float hk[13];
        #pragma unroll
        for (int k = 0; k < 13; k++) hk[k] = hbuf[1][k];
        float s0 = biasB, s1 = 0.0f, s2 = 0.0f, s3 = 0.0f;
        #pragma unroll
        for (int k = 0; k < 13; k++) {
            switch (k & 3) {
                case 0: s0 = fmaf(hk[k], whBs[k], s0); break;
                case 1: s1 = fmaf(hk[k], whBs[k], s1); break;
                case 2: s2 = fmaf(hk[k], whBs[k], s2); break;
                case 3: s3 = fmaf(hk[k], whBs[k], s3); break;
            }
        }
        const float pre  = (s0 + s1) + (s2 + s3);
        const float outv = fmaf(0.5f, tanhap(pre), 0.5f);
        if (lane == 26) ob[TT - 1] = outv;
    }
}

extern "C" void kernel_launch(void* const* d_in, const int* in_sizes, int n_in,
                              void* d_out, int out_size) {
    (void)in_sizes; (void)n_in; (void)out_size;
    const float* x    = (const float*)d_in[0];
    const float* W_ih = (const float*)d_in[1];
    const float* W_hh = (const float*)d_in[2];
    const float* b_ih = (const float*)d_in[3];
    const float* b_hh = (const float*)d_in[4];
    const float* fc_w = (const float*)d_in[5];
    const float* fc_b = (const float*)d_in[6];
    float* out = (float*)d_out;

    lstm_r15<<<NB, 32>>>(x, W_ih, W_hh, b_ih, b_hh, fc_w, fc_b, out);
}

// round 16
// speedup vs baseline: 1.2221x; 1.0477x over previous
#include <cuda_runtime.h>

#define TT 2048
#define NB 512
#define FULLM 0xFFFFFFFFu
typedef unsigned long long ull;

__device__ __forceinline__ float tanhap(float x) {
    float r; asm("tanh.approx.f32 %0, %1;" : "=f"(r) : "f"(x)); return r;
}
__device__ __forceinline__ ull pk(float lo, float hi) {
    ull r; asm("mov.b64 %0, {%1, %2};" : "=l"(r) : "f"(lo), "f"(hi)); return r;
}
__device__ __forceinline__ void upk(ull v, float& lo, float& hi) {
    asm("mov.b64 {%0, %1}, %2;" : "=f"(lo), "=f"(hi) : "l"(v));
}
__device__ __forceinline__ ull fma2(ull a, ull b, ull c) {
    ull d; asm("fma.rn.f32x2 %0, %1, %2, %3;" : "=l"(d) : "l"(a), "l"(b), "l"(c)); return d;
}
__device__ __forceinline__ ull add2(ull a, ull b) {
    ull d; asm("add.rn.f32x2 %0, %1, %2;" : "=l"(d) : "l"(a), "l"(b)); return d;
}
__device__ __forceinline__ ull d2l(double d) { return (ull)__double_as_longlong(d); }

__device__ __forceinline__ void cp_async4(void* smem_dst, const void* gmem_src) {
    unsigned saddr = (unsigned)__cvta_generic_to_shared(smem_dst);
    asm volatile("cp.async.ca.shared.global [%0], [%1], 4;\n"
                 :: "r"(saddr), "l"(gmem_src) : "memory");
}
__device__ __forceinline__ void cp_commit() {
    asm volatile("cp.async.commit_group;\n" ::: "memory");
}
__device__ __forceinline__ void cp_wait4() {
    asm volatile("cp.async.wait_group 4;\n" ::: "memory");
}

// 4-chain packed dot; x terms first (register-resident early), h terms last
// (depth <=2 from h-arrival), then 2-level add tree.
__device__ __forceinline__ float dotg(const ull* xp, const ull* hp,
                                      const ull* wx, const ull* wh,
                                      ull bias, ull z) {
    ull c0 = fma2(xp[0], wx[0], bias);
    ull c1 = fma2(xp[1], wx[1], z);
    ull c2 = fma2(xp[2], wx[2], z);
    ull c3 = fma2(xp[3], wx[3], z);
    c0 = fma2(xp[4], wx[4], c0);
    c1 = fma2(xp[5], wx[5], c1);
    c2 = fma2(xp[6], wx[6], c2);
    c3 = fma2(hp[0], wh[0], c3);
    c0 = fma2(hp[1], wh[1], c0);
    c1 = fma2(hp[2], wh[2], c1);
    c2 = fma2(hp[3], wh[3], c2);
    c3 = fma2(hp[4], wh[4], c3);
    c0 = fma2(hp[5], wh[5], c0);
    c1 = fma2(hp[6], wh[6], c1);
    ull s = add2(add2(c0, c1), add2(c2, c3));
    float lo, hi; upk(s, lo, hi);
    return lo + hi;
}

// h-only dot (tail FC).
__device__ __forceinline__ float dot7(const ull* hp, const ull* w, ull bias, ull z) {
    ull a0 = fma2(hp[0], w[0], bias);
    ull a1 = fma2(hp[1], w[1], z);
    a0 = fma2(hp[2], w[2], a0);
    a1 = fma2(hp[3], w[3], a1);
    a0 = fma2(hp[4], w[4], a0);
    a1 = fma2(hp[5], w[5], a1);
    a0 = fma2(hp[6], w[6], a0);
    ull s = add2(a0, a1);
    float lo, hi; upk(s, lo, hi);
    return lo + hi;
}

__device__ __forceinline__ void ldpairs(const float* row, ull* p) {
    const double2* r = reinterpret_cast<const double2*>(row);
    const double2 q0 = r[0], q1 = r[1], q2 = r[2];
    const double  q3 = *reinterpret_cast<const double*>(row + 12);
    p[0] = d2l(q0.x); p[1] = d2l(q0.y); p[2] = d2l(q1.x); p[3] = d2l(q1.y);
    p[4] = d2l(q2.x); p[5] = d2l(q2.y); p[6] = d2l(q3);
}

__global__ void __launch_bounds__(32)
lstm_r16(const float* __restrict__ x,
         const float* __restrict__ W_ih,
         const float* __restrict__ W_hh,
         const float* __restrict__ b_ih,
         const float* __restrict__ b_hh,
         const float* __restrict__ fc_w,
         const float* __restrict__ fc_b,
         float* __restrict__ out)
{
    __shared__ __align__(16) float xring[8][16];   // pads [13..15] = 0
    __shared__ __align__(16) float hbuf[2][16];    // pads [13..15] = 0

    const int lane = threadIdx.x & 31;
    const int seq  = blockIdx.x;
    const float* xb = x + (size_t)seq * TT * 13;
    float* ob = out + (size_t)seq * TT;

    if (lane < 24) xring[lane / 3][13 + lane % 3] = 0.0f;
    if (lane < 16) { hbuf[0][lane] = 0.0f; hbuf[1][lane] = 0.0f; }

    // Gate assignment: lane L<26: A = gate L (sigmoid; i for L<13, f for L>=13),
    // B = gate 26+L (g=tanh for L<13, o=sigmoid for L>=13).
    // Lane 26: B-dot doubles as the FC head (x-weights 0, h-weights 0.5*fc_w).
    // Sigmoid pre-scale 0.5 folded into weights; act = m*tanh(pre) + a.
    float wiA[13], whA[13], wiB[13], whB[13];
    float biasA = 0.0f, biasB = 0.0f;
    {
        const bool g26 = (lane < 26);
        const float sA = 0.5f;                          // A gates all sigmoid
        const float sB = (lane < 13) ? 1.0f : 0.5f;     // g: tanh, o/fc: sigmoid
        const int rA = g26 ? lane : 0;
        const int rB = g26 ? lane + 26 : 0;
        #pragma unroll
        for (int k = 0; k < 13; k++) {
            wiA[k] = g26 ? sA * W_ih[rA * 13 + k] : 0.0f;
            whA[k] = g26 ? sA * W_hh[rA * 13 + k] : 0.0f;
            wiB[k] = g26 ? sB * W_ih[rB * 13 + k] : 0.0f;
            whB[k] = g26 ? sB * W_hh[rB * 13 + k] : 0.0f;
        }
        if (g26) {
            biasA = sA * (b_ih[rA] + b_hh[rA]);
            biasB = sB * (b_ih[rB] + b_hh[rB]);
        }
        if (lane == 26) {
            #pragma unroll
            for (int k = 0; k < 13; k++) { wiB[k] = 0.0f; whB[k] = 0.5f * fc_w[k]; }
            biasB = 0.5f * fc_b[0];
        }
    }

    ull wxA[7], whAp[7], wxB[7], whBp[7];
    #pragma unroll
    for (int p = 0; p < 6; p++) {
        wxA[p]  = pk(wiA[2*p], wiA[2*p+1]);
        whAp[p] = pk(whA[2*p], whA[2*p+1]);
        wxB[p]  = pk(wiB[2*p], wiB[2*p+1]);
        whBp[p] = pk(whB[2*p], whB[2*p+1]);
    }
    wxA[6]  = pk(wiA[12], 0.0f);
    whAp[6] = pk(whA[12], 0.0f);
    wxB[6]  = pk(wiB[12], 0.0f);
    whBp[6] = pk(whB[12], 0.0f);

    const ull biasPA = pk(biasA, 0.0f);
    const ull biasPB = pk(biasB, 0.0f);
    const ull zero64 = pk(0.0f, 0.0f);

    const float mB = (lane < 13) ? 1.0f : 0.5f;
    const float aB = (lane < 13) ? 0.0f : 0.5f;

    float h = 0.0f, c = 0.0f;

    // Prologue: stage x rows 0..4 (5 commit groups), then pull row 0 to regs.
    #pragma unroll
    for (int t0 = 0; t0 < 5; t0++) {
        if (lane < 13) cp_async4(&xring[t0][lane], xb + t0 * 13 + lane);
        cp_commit();
    }
    cp_wait4();
    __syncwarp();
    ull xcur[7];
    ldpairs(&xring[0][0], xcur);

    for (int t = 0; t < TT; t += 8) {
        #pragma unroll
        for (int u = 0; u < 8; u++) {
            const int tt    = t + u;
            const int wslot = (u + 5) & 7;    // (tt+5) & 7
            const int nslot = (u + 1) & 7;    // (tt+1) & 7
            const int hbr   = (u + 1) & 1;    // holds h_{tt-1}
            const int hbw   = u & 1;

            // Clamped unconditional fetch row (single predicated cp.async).
            int rowc = tt + 5;
            rowc = (rowc > TT - 1) ? (TT - 1) : rowc;
            if (lane < 13)
                cp_async4(&xring[wslot][lane], xb + (size_t)rowc * 13 + lane);
            cp_commit();
            cp_wait4();          // guarantees row tt+1 resident
            __syncwarp();        // x visibility + h_{tt-1} STS visibility

            // h_{tt-1} pairs (critical), then next x row to registers.
            ull hp[7];
            ldpairs(&hbuf[hbr][0], hp);
            ull xnxt[7];
            ldpairs(&xring[nslot][0], xnxt);

            const float preA = dotg(xcur, hp, wxA, whAp, biasPA, zero64);
            const float preB = dotg(xcur, hp, wxB, whBp, biasPB, zero64);

            // Unconditional activation + state update: no divergent region,
            // idle lanes (>=27) run on zeros (bounded, finite).
            const float actA = fmaf(0.5f, tanhap(preA), 0.5f);   // sigm (i / f)
            const float actB = fmaf(mB,   tanhap(preB), aB);     // g / o / FC

            // Lane 26's actB == sigm(fc(h_{tt-1})): emit output tt-1.
            // tt=0 writes FC(h_{-1}) garbage to ob[0]; tt=1 overwrites it
            // (same thread, same address, program order).
            int ttm = tt - 1;
            ttm = (ttm < 0) ? 0 : ttm;
            if (lane == 26) ob[ttm] = actB;      // single predicated STG

            // Ship activated f / o from lane 13+j to lane j.
            const float fg = __shfl_sync(FULLM, actA, (lane + 13) & 31);
            const float og = __shfl_sync(FULLM, actB, (lane + 13) & 31);

            c = fmaf(fg, c, actA * actB);
            h = og * tanhap(c);
            if (lane < 13) hbuf[hbw][lane] = h;  // single predicated STS

            #pragma unroll
            for (int p = 0; p < 7; p++) xcur[p] = xnxt[p];
        }
    }

    // Tail: ob[TT-1] = sigm(fc(h_{TT-1})); h_{TT-1} lives in hbuf[1].
    __syncwarp();
    {
        ull hp[7];
        ldpairs(&hbuf[1][0], hp);
        const float pre  = dot7(hp, whBp, biasPB, zero64);   // lane 26: 0.5*fc
        const float outv = fmaf(0.5f, tanhap(pre), 0.5f);
        if (lane == 26) ob[TT - 1] = outv;
    }
}

extern "C" void kernel_launch(void* const* d_in, const int* in_sizes, int n_in,
                              void* d_out, int out_size) {
    (void)in_sizes; (void)n_in; (void)out_size;
    const float* x    = (const float*)d_in[0];
    const float* W_ih = (const float*)d_in[1];
    const float* W_hh = (const float*)d_in[2];
    const float* b_ih = (const float*)d_in[3];
    const float* b_hh = (const float*)d_in[4];
    const float* fc_w = (const float*)d_in[5];
    const float* fc_b = (const float*)d_in[6];
    float* out = (float*)d_out;

    lstm_r16<<<NB, 32>>>(x, W_ih, W_hh, b_ih, b_hh, fc_w, fc_b, out);
}

// round 17
// speedup vs baseline: 1.2813x; 1.0485x over previous
#include <cuda_runtime.h>

#define TT 2048
#define NB 512
#define FULLM 0xFFFFFFFFu
typedef unsigned long long ull;

__device__ __forceinline__ float tanhap(float x) {
    float r; asm("tanh.approx.f32 %0, %1;" : "=f"(r) : "f"(x)); return r;
}
__device__ __forceinline__ ull pk(float lo, float hi) {
    ull r; asm("mov.b64 %0, {%1, %2};" : "=l"(r) : "f"(lo), "f"(hi)); return r;
}
__device__ __forceinline__ void upk(ull v, float& lo, float& hi) {
    asm("mov.b64 {%0, %1}, %2;" : "=f"(lo), "=f"(hi) : "l"(v));
}
__device__ __forceinline__ ull fma2(ull a, ull b, ull c) {
    ull d; asm("fma.rn.f32x2 %0, %1, %2, %3;" : "=l"(d) : "l"(a), "l"(b), "l"(c)); return d;
}
__device__ __forceinline__ ull add2(ull a, ull b) {
    ull d; asm("add.rn.f32x2 %0, %1, %2;" : "=l"(d) : "l"(a), "l"(b)); return d;
}
__device__ __forceinline__ ull d2l(double d) { return (ull)__double_as_longlong(d); }

__device__ __forceinline__ void cp_async4(void* smem_dst, const void* gmem_src) {
    unsigned saddr = (unsigned)__cvta_generic_to_shared(smem_dst);
    asm volatile("cp.async.ca.shared.global [%0], [%1], 4;\n"
                 :: "r"(saddr), "l"(gmem_src) : "memory");
}
__device__ __forceinline__ void cp_commit() {
    asm volatile("cp.async.commit_group;\n" ::: "memory");
}
__device__ __forceinline__ void cp_wait4() {
    asm volatile("cp.async.wait_group 4;\n" ::: "memory");
}

// Compiler-fenced h publish: asm volatile + memory clobber pins this store as
// a one-point scheduling barrier (later h-loads cannot hoist above it), while
// all surrounding plain loads/FMAs keep full scheduling freedom. The warp-wide
// STS retires through the in-order LSU before any later LDS issues, so no
// __syncwarp is needed (R8-validated on hardware).
__device__ __forceinline__ void sts_h(unsigned addr, float v) {
    asm volatile("st.shared.f32 [%0], %1;" :: "r"(addr), "f"(v) : "memory");
}

// 4-chain packed dot; x terms first (register-resident early), h terms last
// (depth <=2 from h-arrival), then 2-level add tree.
__device__ __forceinline__ float dotg(const ull* xp, const ull* hp,
                                      const ull* wx, const ull* wh,
                                      ull bias, ull z) {
    ull c0 = fma2(xp[0], wx[0], bias);
    ull c1 = fma2(xp[1], wx[1], z);
    ull c2 = fma2(xp[2], wx[2], z);
    ull c3 = fma2(xp[3], wx[3], z);
    c0 = fma2(xp[4], wx[4], c0);
    c1 = fma2(xp[5], wx[5], c1);
    c2 = fma2(xp[6], wx[6], c2);
    c3 = fma2(hp[0], wh[0], c3);
    c0 = fma2(hp[1], wh[1], c0);
    c1 = fma2(hp[2], wh[2], c1);
    c2 = fma2(hp[3], wh[3], c2);
    c3 = fma2(hp[4], wh[4], c3);
    c0 = fma2(hp[5], wh[5], c0);
    c1 = fma2(hp[6], wh[6], c1);
    ull s = add2(add2(c0, c1), add2(c2, c3));
    float lo, hi; upk(s, lo, hi);
    return lo + hi;
}

// h-only dot (tail FC).
__device__ __forceinline__ float dot7(const ull* hp, const ull* w, ull bias, ull z) {
    ull a0 = fma2(hp[0], w[0], bias);
    ull a1 = fma2(hp[1], w[1], z);
    a0 = fma2(hp[2], w[2], a0);
    a1 = fma2(hp[3], w[3], a1);
    a0 = fma2(hp[4], w[4], a0);
    a1 = fma2(hp[5], w[5], a1);
    a0 = fma2(hp[6], w[6], a0);
    ull s = add2(a0, a1);
    float lo, hi; upk(s, lo, hi);
    return lo + hi;
}

__device__ __forceinline__ void ldpairs(const float* row, ull* p) {
    const double2* r = reinterpret_cast<const double2*>(row);
    const double2 q0 = r[0], q1 = r[1], q2 = r[2];
    const double  q3 = *reinterpret_cast<const double*>(row + 12);
    p[0] = d2l(q0.x); p[1] = d2l(q0.y); p[2] = d2l(q1.x); p[3] = d2l(q1.y);
    p[4] = d2l(q2.x); p[5] = d2l(q2.y); p[6] = d2l(q3);
}

__global__ void __launch_bounds__(32)
lstm_r17(const float* __restrict__ x,
         const float* __restrict__ W_ih,
         const float* __restrict__ W_hh,
         const float* __restrict__ b_ih,
         const float* __restrict__ b_hh,
         const float* __restrict__ fc_w,
         const float* __restrict__ fc_b,
         float* __restrict__ out)
{
    __shared__ __align__(16) float xring[8][16];   // pads [13..15] = 0
    __shared__ __align__(16) float hbuf[2][16];    // pads [13..15] = 0

    const int lane = threadIdx.x & 31;
    const int seq  = blockIdx.x;
    const float* xb = x + (size_t)seq * TT * 13;
    float* ob = out + (size_t)seq * TT;

    const unsigned hda = (unsigned)__cvta_generic_to_shared(&hbuf[0][0]);

    if (lane < 24) xring[lane / 3][13 + lane % 3] = 0.0f;
    if (lane < 16) { hbuf[0][lane] = 0.0f; hbuf[1][lane] = 0.0f; }

    // Gate assignment: lane L<26: A = gate L (sigmoid; i for L<13, f for L>=13),
    // B = gate 26+L (g=tanh for L<13, o=sigmoid for L>=13).
    // Lane 26: B-dot doubles as the FC head (x-weights 0, h-weights 0.5*fc_w).
    // Sigmoid pre-scale 0.5 folded into weights; act = m*tanh(pre) + a.
    float wiA[13], whA[13], wiB[13], whB[13];
    float biasA = 0.0f, biasB = 0.0f;
    {
        const bool g26 = (lane < 26);
        const float sA = 0.5f;
        const float sB = (lane < 13) ? 1.0f : 0.5f;
        const int rA = g26 ? lane : 0;
        const int rB = g26 ? lane + 26 : 0;
        #pragma unroll
        for (int k = 0; k < 13; k++) {
            wiA[k] = g26 ? sA * W_ih[rA * 13 + k] : 0.0f;
            whA[k] = g26 ? sA * W_hh[rA * 13 + k] : 0.0f;
            wiB[k] = g26 ? sB * W_ih[rB * 13 + k] : 0.0f;
            whB[k] = g26 ? sB * W_hh[rB * 13 + k] : 0.0f;
        }
        if (g26) {
            biasA = sA * (b_ih[rA] + b_hh[rA]);
            biasB = sB * (b_ih[rB] + b_hh[rB]);
        }
        if (lane == 26) {
            #pragma unroll
            for (int k = 0; k < 13; k++) { wiB[k] = 0.0f; whB[k] = 0.5f * fc_w[k]; }
            biasB = 0.5f * fc_b[0];
        }
    }

    ull wxA[7], whAp[7], wxB[7], whBp[7];
    #pragma unroll
    for (int p = 0; p < 6; p++) {
        wxA[p]  = pk(wiA[2*p], wiA[2*p+1]);
        whAp[p] = pk(whA[2*p], whA[2*p+1]);
        wxB[p]  = pk(wiB[2*p], wiB[2*p+1]);
        whBp[p] = pk(whB[2*p], whB[2*p+1]);
    }
    wxA[6]  = pk(wiA[12], 0.0f);
    whAp[6] = pk(whA[12], 0.0f);
    wxB[6]  = pk(wiB[12], 0.0f);
    whBp[6] = pk(whB[12], 0.0f);

    const ull biasPA = pk(biasA, 0.0f);
    const ull biasPB = pk(biasB, 0.0f);
    const ull zero64 = pk(0.0f, 0.0f);

    const float mB = (lane < 13) ? 1.0f : 0.5f;
    const float aB = (lane < 13) ? 0.0f : 0.5f;

    float h = 0.0f, c = 0.0f;

    // Prologue: stage x rows 0..4 (5 commit groups), then pull row 0 to regs.
    #pragma unroll
    for (int t0 = 0; t0 < 5; t0++) {
        if (lane < 13) cp_async4(&xring[t0][lane], xb + t0 * 13 + lane);
        cp_commit();
    }
    cp_wait4();
    __syncwarp();
    ull xcur[7];
    ldpairs(&xring[0][0], xcur);

    for (int t = 0; t < TT; t += 8) {
        #pragma unroll
        for (int u = 0; u < 8; u++) {
            const int tt    = t + u;
            const int wslot = (u + 5) & 7;    // (tt+5) & 7
            const int nslot = (u + 1) & 7;    // (tt+1) & 7
            const int hbr   = (u + 1) & 1;    // holds h_{tt-1}
            const int hbw   = u & 1;

            if (lane < 13 && tt + 5 < TT)
                cp_async4(&xring[wslot][lane], xb + (size_t)(tt + 5) * 13 + lane);
            cp_commit();
            cp_wait4();          // row tt+1 resident (warp-wide retire) +
                                 // compiler memory fence for the x reads below

            // h_{tt-1} pairs (critical), then next x row to registers.
            // No __syncwarp: the previous step's volatile STS h is the
            // compiler fence; the in-order LSU is the hardware fence.
            ull hp[7];
            ldpairs(&hbuf[hbr][0], hp);
            ull xnxt[7];
            ldpairs(&xring[nslot][0], xnxt);

            const float preA = dotg(xcur, hp, wxA, whAp, biasPA, zero64);
            const float preB = dotg(xcur, hp, wxB, whBp, biasPB, zero64);

            const float actA = fmaf(0.5f, tanhap(preA), 0.5f);   // sigm (i / f)
            const float actB = fmaf(mB,   tanhap(preB), aB);     // g / o / FC

            // Lane 26's actB == sigm(fc(h_{tt-1})): emit output tt-1.
            if (lane == 26 && tt > 0) ob[tt - 1] = actB;

            // Ship activated f / o from lane 13+j to lane j.
            const float fg = __shfl_sync(FULLM, actA, (lane + 13) & 31);
            const float og = __shfl_sync(FULLM, actB, (lane + 13) & 31);

            c = fmaf(fg, c, actA * actB);
            h = og * tanhap(c);
            if (lane < 13) sts_h(hda + hbw * 64 + lane * 4, h);

            #pragma unroll
            for (int p = 0; p < 7; p++) xcur[p] = xnxt[p];
        }
    }

    // Tail: ob[TT-1] = sigm(fc(h_{TT-1})); h_{TT-1} lives in hbuf[1].
    __syncwarp();
    {
        ull hp[7];
        ldpairs(&hbuf[1][0], hp);
        const float pre  = dot7(hp, whBp, biasPB, zero64);   // lane 26: 0.5*fc
        const float outv = fmaf(0.5f, tanhap(pre), 0.5f);
        if (lane == 26) ob[TT - 1] = outv;
    }
}

extern "C" void kernel_launch(void* const* d_in, const int* in_sizes, int n_in,
                              void* d_out, int out_size) {
    (void)in_sizes; (void)n_in; (void)out_size;
    const float* x    = (const float*)d_in[0];
    const float* W_ih = (const float*)d_in[1];
    const float* W_hh = (const float*)d_in[2];
    const float* b_ih = (const float*)d_in[3];
    const float* b_hh = (const float*)d_in[4];
    const float* fc_w = (const float*)d_in[5];
    const float* fc_b = (const float*)d_in[6];
    float* out = (float*)d_out;

    lstm_r17<<<NB, 32>>>(x, W_ih, W_hh, b_ih, b_hh, fc_w, fc_b, out);
}